// round 1
// baseline (speedup 1.0000x reference)
#include <cuda_runtime.h>
#include <math.h>

#define BB 16
#define GG 2048
#define CC 128
#define KK 16
#define AS_LD 132   // padded leading dim for transposed A tile (floats)

// Scratch: knn indices (allocation-free rule -> device global)
__device__ int g_knn[BB * GG * KK];

// ---------------------------------------------------------------------------
// Kernel 1: exact KNN (top-16 smallest d2 incl. self) per query.
// One thread = one query. Batch xyz staged in SMEM as SoA (broadcast reads).
// d2 uses the same sq[i]+sq[j]-2*dot expansion as the reference.
// ---------------------------------------------------------------------------
__device__ __forceinline__ void insert16(float (&dist)[KK], int (&idx)[KK],
                                         float d, int i) {
    if (d < dist[KK - 1]) {
        float cd = d; int ci = i;
#pragma unroll
        for (int k = 0; k < KK; ++k) {
            bool lt = cd < dist[k];
            float td = dist[k]; int ti = idx[k];
            if (lt) { dist[k] = cd; idx[k] = ci; cd = td; ci = ti; }
        }
    }
}

__global__ __launch_bounds__(128) void knn_kernel(const float* __restrict__ xyz) {
    __shared__ __align__(16) float xs[GG];
    __shared__ __align__(16) float ys[GG];
    __shared__ __align__(16) float zs[GG];
    __shared__ __align__(16) float ss[GG];

    const int b = blockIdx.y;
    const float* p = xyz + (size_t)b * GG * 3;
    for (int i = threadIdx.x; i < GG; i += 128) {
        float x = p[i * 3 + 0], y = p[i * 3 + 1], z = p[i * 3 + 2];
        xs[i] = x; ys[i] = y; zs[i] = z;
        ss[i] = x * x + y * y + z * z;
    }
    __syncthreads();

    const int q = blockIdx.x * 128 + threadIdx.x;   // 0..2047 within batch
    const float qx = xs[q], qy = ys[q], qz = zs[q], qs = ss[q];

    float dist[KK]; int idx[KK];
#pragma unroll
    for (int k = 0; k < KK; ++k) { dist[k] = 3.4e38f; idx[k] = 0; }

    for (int i = 0; i < GG; i += 4) {
        const float4 X = *reinterpret_cast<const float4*>(xs + i);
        const float4 Y = *reinterpret_cast<const float4*>(ys + i);
        const float4 Z = *reinterpret_cast<const float4*>(zs + i);
        const float4 S = *reinterpret_cast<const float4*>(ss + i);

        float t0 = fmaf(qx, X.x, fmaf(qy, Y.x, qz * Z.x));
        float d0 = fmaf(-2.f, t0, qs + S.x);
        insert16(dist, idx, d0, i + 0);

        float t1 = fmaf(qx, X.y, fmaf(qy, Y.y, qz * Z.y));
        float d1 = fmaf(-2.f, t1, qs + S.y);
        insert16(dist, idx, d1, i + 1);

        float t2 = fmaf(qx, X.z, fmaf(qy, Y.z, qz * Z.z));
        float d2 = fmaf(-2.f, t2, qs + S.z);
        insert16(dist, idx, d2, i + 2);

        float t3 = fmaf(qx, X.w, fmaf(qy, Y.w, qz * Z.w));
        float d3 = fmaf(-2.f, t3, qs + S.w);
        insert16(dist, idx, d3, i + 3);
    }

    int* o = g_knn + ((size_t)b * GG + q) * KK;
#pragma unroll
    for (int k = 0; k < KK; ++k) o[k] = idx[k];
}

// ---------------------------------------------------------------------------
// Kernel 2: fused gather + L2-pool + (Linear -> exact GELU -> Linear).
// Block = 256 threads, 128-row tile. A tile stored TRANSPOSED [c][r] (pad 132)
// so both GEMM operand reads are conflict-free LDS.128. 8x8 register micro-tile.
// W1 then W2 staged in the same 64KB SMEM buffer; H overwrites A in place.
// ---------------------------------------------------------------------------
#define SMEM_FLOATS (CC * AS_LD + CC * CC + 2 * CC)
#define SMEM_BYTES  (SMEM_FLOATS * 4 + 128 * KK * 4)

__device__ __forceinline__ void gemm_8x8(const float* __restrict__ As,
                                         const float* __restrict__ Ws,
                                         int r0, int j0, float (&acc)[8][8]) {
#pragma unroll
    for (int ii = 0; ii < 8; ++ii)
#pragma unroll
        for (int jj = 0; jj < 8; ++jj) acc[ii][jj] = 0.f;

    for (int c = 0; c < CC; ++c) {
        const float4 a0 = *reinterpret_cast<const float4*>(As + c * AS_LD + r0);
        const float4 a1 = *reinterpret_cast<const float4*>(As + c * AS_LD + r0 + 4);
        const float4 w0 = *reinterpret_cast<const float4*>(Ws + c * CC + j0);
        const float4 w1 = *reinterpret_cast<const float4*>(Ws + c * CC + j0 + 4);
        const float av[8] = {a0.x, a0.y, a0.z, a0.w, a1.x, a1.y, a1.z, a1.w};
        const float wv[8] = {w0.x, w0.y, w0.z, w0.w, w1.x, w1.y, w1.z, w1.w};
#pragma unroll
        for (int ii = 0; ii < 8; ++ii)
#pragma unroll
            for (int jj = 0; jj < 8; ++jj)
                acc[ii][jj] = fmaf(av[ii], wv[jj], acc[ii][jj]);
    }
}

__global__ __launch_bounds__(256) void mlp_kernel(const float* __restrict__ feat,
                                                  const float* __restrict__ W1,
                                                  const float* __restrict__ b1,
                                                  const float* __restrict__ W2,
                                                  const float* __restrict__ b2,
                                                  float* __restrict__ out) {
    extern __shared__ __align__(16) float sm[];
    float* As   = sm;                    // CC * AS_LD  (transposed A / H tile)
    float* Ws   = As + CC * AS_LD;       // CC * CC     (W1 then W2)
    float* bs   = Ws + CC * CC;          // 2 * CC      (b1, b2)
    int*   sidx = (int*)(bs + 2 * CC);   // 128 * KK

    const int tid = threadIdx.x;
    const int rowBase = blockIdx.x * 128;        // global query row
    const int b = rowBase >> 11;                  // / GG
    const float* fb = feat + (size_t)b * GG * CC;

    // stage knn indices, W1, biases
    for (int i = tid; i < 128 * KK; i += 256) sidx[i] = g_knn[(size_t)rowBase * KK + i];
    for (int i = tid; i < CC * CC / 4; i += 256)
        ((float4*)Ws)[i] = ((const float4*)W1)[i];
    if (tid < CC) { bs[tid] = b1[tid]; bs[CC + tid] = b2[tid]; }
    __syncthreads();

    // gather + pool -> As[c][r] (transposed). warp = row-within-pass, lane = c/4.
    {
        const int lane = tid & 31, warp = tid >> 5;
        for (int pass = 0; pass < 16; ++pass) {
            const int r = pass * 8 + warp;
            const int* ip = sidx + r * KK;
            float4 acc = make_float4(0.f, 0.f, 0.f, 0.f);
#pragma unroll
            for (int k = 0; k < KK; ++k) {
                const float4 f = *reinterpret_cast<const float4*>(
                    fb + (size_t)ip[k] * CC + lane * 4);
                acc.x = fmaf(f.x, f.x, acc.x);
                acc.y = fmaf(f.y, f.y, acc.y);
                acc.z = fmaf(f.z, f.z, acc.z);
                acc.w = fmaf(f.w, f.w, acc.w);
            }
            const int c0 = lane * 4;
            As[(c0 + 0) * AS_LD + r] = sqrtf(acc.x);
            As[(c0 + 1) * AS_LD + r] = sqrtf(acc.y);
            As[(c0 + 2) * AS_LD + r] = sqrtf(acc.z);
            As[(c0 + 3) * AS_LD + r] = sqrtf(acc.w);
        }
    }
    __syncthreads();

    const int ty = tid >> 4, tx = tid & 15;
    const int r0 = ty * 8, j0 = tx * 8;

    float acc[8][8];
    gemm_8x8(As, Ws, r0, j0, acc);

    // exact GELU in registers
#pragma unroll
    for (int ii = 0; ii < 8; ++ii)
#pragma unroll
        for (int jj = 0; jj < 8; ++jj) {
            float v = acc[ii][jj] + bs[j0 + jj];
            acc[ii][jj] = 0.5f * v * (1.f + erff(v * 0.70710678118654752f));
        }
    __syncthreads();   // all reads of As/Ws done

    // H^T into As; W2 into Ws
#pragma unroll
    for (int ii = 0; ii < 8; ++ii)
#pragma unroll
        for (int jj = 0; jj < 8; ++jj)
            As[(j0 + jj) * AS_LD + (r0 + ii)] = acc[ii][jj];
    for (int i = tid; i < CC * CC / 4; i += 256)
        ((float4*)Ws)[i] = ((const float4*)W2)[i];
    __syncthreads();

    float acc2[8][8];
    gemm_8x8(As, Ws, r0, j0, acc2);

#pragma unroll
    for (int ii = 0; ii < 8; ++ii) {
        float* op = out + (size_t)(rowBase + r0 + ii) * CC + j0;
        float4 o0 = make_float4(acc2[ii][0] + bs[CC + j0 + 0],
                                acc2[ii][1] + bs[CC + j0 + 1],
                                acc2[ii][2] + bs[CC + j0 + 2],
                                acc2[ii][3] + bs[CC + j0 + 3]);
        float4 o1 = make_float4(acc2[ii][4] + bs[CC + j0 + 4],
                                acc2[ii][5] + bs[CC + j0 + 5],
                                acc2[ii][6] + bs[CC + j0 + 6],
                                acc2[ii][7] + bs[CC + j0 + 7]);
        *reinterpret_cast<float4*>(op)     = o0;
        *reinterpret_cast<float4*>(op + 4) = o1;
    }
}

// ---------------------------------------------------------------------------
extern "C" void kernel_launch(void* const* d_in, const int* in_sizes, int n_in,
                              void* d_out, int out_size) {
    const float* xyz  = (const float*)d_in[0];
    const float* feat = (const float*)d_in[1];
    const float* W1   = (const float*)d_in[2];
    const float* b1   = (const float*)d_in[3];
    const float* W2   = (const float*)d_in[4];
    const float* b2   = (const float*)d_in[5];
    float* out = (float*)d_out;

    dim3 gknn(GG / 128, BB);
    knn_kernel<<<gknn, 128>>>(xyz);

    cudaFuncSetAttribute(mlp_kernel, cudaFuncAttributeMaxDynamicSharedMemorySize,
                         SMEM_BYTES);
    mlp_kernel<<<(BB * GG) / 128, 256, SMEM_BYTES>>>(feat, W1, b1, W2, b2, out);
}

// round 2
// speedup vs baseline: 1.2780x; 1.2780x over previous
#include <cuda_runtime.h>
#include <math.h>

#define BB 16
#define GG 2048
#define CC 128
#define KK 16
#define TM 64          // rows per mlp block
#define QW 8           // queries (warps) per knn block

__device__ int g_knn[BB * GG * KK];

// ---------------------------------------------------------------------------
// f32x2 helpers (sm_103a packed fp32)
// ---------------------------------------------------------------------------
__device__ __forceinline__ unsigned long long dup2(float x) {
    unsigned long long r; unsigned a = __float_as_uint(x);
    asm("mov.b64 %0, {%1, %1};" : "=l"(r) : "r"(a));
    return r;
}
__device__ __forceinline__ float2 unpack2(unsigned long long v) {
    unsigned lo, hi;
    asm("mov.b64 {%0, %1}, %2;" : "=r"(lo), "=r"(hi) : "l"(v));
    return make_float2(__uint_as_float(lo), __uint_as_float(hi));
}
#define FMA2(acc, a, b) \
    asm("fma.rn.f32x2 %0, %1, %2, %0;" : "+l"(acc) : "l"(a), "l"(b))

// ---------------------------------------------------------------------------
// KNN: warp per query, exact radix select on ordered-uint(d2).
// ---------------------------------------------------------------------------
__device__ __forceinline__ unsigned ordered_key(float d) {
    unsigned u = __float_as_uint(d);
    unsigned m = ((unsigned)(((int)u) >> 31)) | 0x80000000u;
    return u ^ m;
}

// find digit D (0..255) such that cumExcl < need <= cumIncl over hist[256]
__device__ __forceinline__ void scan_select(const unsigned* hist, int lane,
                                            unsigned need, unsigned& D,
                                            unsigned& base, unsigned& cnt) {
    unsigned c8[8]; unsigned lsum = 0;
#pragma unroll
    for (int k = 0; k < 8; ++k) { c8[k] = hist[lane * 8 + k]; lsum += c8[k]; }
    unsigned run = lsum;
#pragma unroll
    for (int off = 1; off < 32; off <<= 1) {
        unsigned n = __shfl_up_sync(0xffffffffu, run, off);
        if (lane >= off) run += n;
    }
    unsigned excl = run - lsum;
    bool has = (excl < need) && (run >= need);
    unsigned m = __ballot_sync(0xffffffffu, has);
    int src = __ffs(m) - 1;
    unsigned d = 0, b = 0, cn = 0;
    if (lane == src) {
        unsigned r = excl; bool found = false;
#pragma unroll
        for (int k = 0; k < 8; ++k) {
            if (!found) {
                if (r + c8[k] >= need) { d = lane * 8 + k; b = r; cn = c8[k]; found = true; }
                else r += c8[k];
            }
        }
    }
    D    = __shfl_sync(0xffffffffu, d,  src);
    base = __shfl_sync(0xffffffffu, b,  src);
    cnt  = __shfl_sync(0xffffffffu, cn, src);
}

__global__ __launch_bounds__(256) void knn_kernel(const float* __restrict__ xyz) {
    extern __shared__ unsigned char ksm[];
    float4*   pts     = (float4*)ksm;                          // 2048 * 16B = 32KB
    unsigned* keysAll = (unsigned*)(ksm + GG * 16);            // 8 * 2048 * 4 = 64KB
    unsigned* histAll = (unsigned*)(ksm + GG * 16 + QW * GG * 4); // 8 * 256 * 4 = 8KB

    const int tid = threadIdx.x;
    const int b = blockIdx.y;
    const float* p = xyz + (size_t)b * GG * 3;

    for (int i = tid; i < GG; i += 256) {
        float x = p[i * 3 + 0], y = p[i * 3 + 1], z = p[i * 3 + 2];
        pts[i] = make_float4(x, y, z, x * x + y * y + z * z);
    }
    __syncthreads();

    const int w = tid >> 5, lane = tid & 31;
    const unsigned lmask_lt = (1u << lane) - 1u;
    unsigned* keys = keysAll + w * GG;
    unsigned* hist = histAll + w * 256;

    const int q = blockIdx.x * QW + w;
    const float4 qp = pts[q];
    const float qx = qp.x, qy = qp.y, qz = qp.z, qs = qp.w;

    // ---- pass 1: distances -> keys, level-1 histogram (bits [31:24]) ----
#pragma unroll
    for (int k = 0; k < 8; ++k) hist[lane * 8 + k] = 0;
    __syncwarp();
#pragma unroll 4
    for (int j = 0; j < GG / 32; ++j) {
        int c = j * 32 + lane;
        float4 pc = pts[c];
        float t = fmaf(qx, pc.x, fmaf(qy, pc.y, qz * pc.z));
        float d = fmaf(-2.f, t, qs + pc.w);
        unsigned u = ordered_key(d);
        keys[c] = u;
        atomicAdd(&hist[u >> 24], 1u);
    }
    __syncwarp();

    unsigned need = KK;
    unsigned D, base, cnt;
    scan_select(hist, lane, need, D, base, cnt);
    unsigned prefix = D;
    need -= base;
    int S = 24;

    // ---- deeper levels (early exit when whole bin selected) ----
    if (need != cnt) {
        for (int s = 16; s >= 0; s -= 8) {
#pragma unroll
            for (int k = 0; k < 8; ++k) hist[lane * 8 + k] = 0;
            __syncwarp();
#pragma unroll 4
            for (int j = 0; j < GG / 32; ++j) {
                unsigned u = keys[j * 32 + lane];
                if ((u >> (s + 8)) == prefix) atomicAdd(&hist[(u >> s) & 0xFFu], 1u);
            }
            __syncwarp();
            scan_select(hist, lane, need, D, base, cnt);
            prefix = (prefix << 8) | D;
            need -= base;
            S = s;
            if (need == cnt || s == 0) break;
        }
    }
    const unsigned P = prefix, t = need;

    // ---- final pass: emit 16 indices (key>>S < P, plus first t ties) ----
    unsigned tieCnt = 0, outCnt = 0;
    int* outp = g_knn + ((size_t)b * GG + q) * KK;
    for (int j = 0; j < GG / 32; ++j) {
        int c = j * 32 + lane;
        unsigned hi = keys[c] >> S;
        bool selLow = hi < P;
        bool isTie = (hi == P);
        unsigned mt = __ballot_sync(0xffffffffu, isTie);
        bool selTie = isTie && (tieCnt + __popc(mt & lmask_lt) < t);
        tieCnt += __popc(mt);
        bool sel = selLow || selTie;
        unsigned ms = __ballot_sync(0xffffffffu, sel);
        if (sel) outp[outCnt + __popc(ms & lmask_lt)] = c;
        outCnt += __popc(ms);
    }
}

// ---------------------------------------------------------------------------
// MLP: fused gather + L2 pool + Linear -> GELU -> Linear. Row-major A tile,
// f32x2 packed FMAs, 64-row tiles (2 blocks/SM).
// ---------------------------------------------------------------------------
#define MLP_SMEM (TM * CC * 4 + CC * CC * 4 + 2 * CC * 4 + TM * KK * 4)

__device__ __forceinline__ void gemm64(const float* __restrict__ As,
                                       const float* __restrict__ Ws,
                                       int r0, int j0,
                                       unsigned long long (&acc)[4][4]) {
#pragma unroll
    for (int i = 0; i < 4; ++i)
#pragma unroll
        for (int pp = 0; pp < 4; ++pp) acc[i][pp] = 0ULL;

    for (int c = 0; c < CC; ++c) {
        const ulonglong2* wp = reinterpret_cast<const ulonglong2*>(Ws + c * CC + j0);
        ulonglong2 wA = wp[0], wB = wp[1];
        unsigned long long wv[4] = {wA.x, wA.y, wB.x, wB.y};
        unsigned long long av[4];
#pragma unroll
        for (int i = 0; i < 4; ++i) av[i] = dup2(As[(r0 + i) * CC + c]);
#pragma unroll
        for (int i = 0; i < 4; ++i)
#pragma unroll
            for (int pp = 0; pp < 4; ++pp)
                FMA2(acc[i][pp], av[i], wv[pp]);
    }
}

__global__ __launch_bounds__(256) void mlp_kernel(const float* __restrict__ feat,
                                                  const float* __restrict__ W1,
                                                  const float* __restrict__ b1,
                                                  const float* __restrict__ W2,
                                                  const float* __restrict__ b2,
                                                  float* __restrict__ out) {
    extern __shared__ __align__(16) float sm[];
    float* As   = sm;                  // TM * CC (row-major)
    float* Ws   = As + TM * CC;        // CC * CC
    float* bs   = Ws + CC * CC;        // 2 * CC
    int*   sidx = (int*)(bs + 2 * CC); // TM * KK

    const int tid = threadIdx.x;
    const int rowBase = blockIdx.x * TM;
    const int b = rowBase >> 11;
    const float* fb = feat + (size_t)b * GG * CC;

    for (int i = tid; i < TM * KK; i += 256) sidx[i] = g_knn[(size_t)rowBase * KK + i];
    for (int i = tid; i < CC * CC / 4; i += 256)
        ((float4*)Ws)[i] = ((const float4*)W1)[i];
    if (tid < CC) { bs[tid] = b1[tid]; bs[CC + tid] = b2[tid]; }
    __syncthreads();

    // gather + pool -> As[r][c] (row-major, conflict-free float4 STS)
    {
        const int lane = tid & 31, warp = tid >> 5;
        for (int pass = 0; pass < TM / 8; ++pass) {
            const int r = pass * 8 + warp;
            const int* ip = sidx + r * KK;
            float4 acc = make_float4(0.f, 0.f, 0.f, 0.f);
#pragma unroll
            for (int k = 0; k < KK; ++k) {
                const float4 f = *reinterpret_cast<const float4*>(
                    fb + (size_t)ip[k] * CC + lane * 4);
                acc.x = fmaf(f.x, f.x, acc.x);
                acc.y = fmaf(f.y, f.y, acc.y);
                acc.z = fmaf(f.z, f.z, acc.z);
                acc.w = fmaf(f.w, f.w, acc.w);
            }
            acc.x = sqrtf(acc.x); acc.y = sqrtf(acc.y);
            acc.z = sqrtf(acc.z); acc.w = sqrtf(acc.w);
            *reinterpret_cast<float4*>(As + r * CC + lane * 4) = acc;
        }
    }
    __syncthreads();

    const int ty = tid >> 4, tx = tid & 15;
    const int r0 = ty * 4, j0 = tx * 8;

    unsigned long long acc[4][4];
    gemm64(As, Ws, r0, j0, acc);

    // GELU epilogue in registers
    float g[4][8];
#pragma unroll
    for (int i = 0; i < 4; ++i)
#pragma unroll
        for (int pp = 0; pp < 4; ++pp) {
            float2 v = unpack2(acc[i][pp]);
            float vx = v.x + bs[j0 + pp * 2 + 0];
            float vy = v.y + bs[j0 + pp * 2 + 1];
            g[i][pp * 2 + 0] = 0.5f * vx * (1.f + erff(vx * 0.70710678118654752f));
            g[i][pp * 2 + 1] = 0.5f * vy * (1.f + erff(vy * 0.70710678118654752f));
        }
    __syncthreads();   // GEMM1 reads of As/Ws complete

    // H into As (row-major), W2 into Ws
#pragma unroll
    for (int i = 0; i < 4; ++i) {
        float* hp = As + (r0 + i) * CC + j0;
        *reinterpret_cast<float4*>(hp)     = make_float4(g[i][0], g[i][1], g[i][2], g[i][3]);
        *reinterpret_cast<float4*>(hp + 4) = make_float4(g[i][4], g[i][5], g[i][6], g[i][7]);
    }
    for (int i = tid; i < CC * CC / 4; i += 256)
        ((float4*)Ws)[i] = ((const float4*)W2)[i];
    __syncthreads();

    unsigned long long acc2[4][4];
    gemm64(As, Ws, r0, j0, acc2);

#pragma unroll
    for (int i = 0; i < 4; ++i) {
        float o[8];
#pragma unroll
        for (int pp = 0; pp < 4; ++pp) {
            float2 v = unpack2(acc2[i][pp]);
            o[pp * 2 + 0] = v.x + bs[CC + j0 + pp * 2 + 0];
            o[pp * 2 + 1] = v.y + bs[CC + j0 + pp * 2 + 1];
        }
        float* op = out + (size_t)(rowBase + r0 + i) * CC + j0;
        *reinterpret_cast<float4*>(op)     = make_float4(o[0], o[1], o[2], o[3]);
        *reinterpret_cast<float4*>(op + 4) = make_float4(o[4], o[5], o[6], o[7]);
    }
}

// ---------------------------------------------------------------------------
extern "C" void kernel_launch(void* const* d_in, const int* in_sizes, int n_in,
                              void* d_out, int out_size) {
    const float* xyz  = (const float*)d_in[0];
    const float* feat = (const float*)d_in[1];
    const float* W1   = (const float*)d_in[2];
    const float* b1   = (const float*)d_in[3];
    const float* W2   = (const float*)d_in[4];
    const float* b2   = (const float*)d_in[5];
    float* out = (float*)d_out;

    const int KNN_SMEM = GG * 16 + QW * GG * 4 + QW * 256 * 4;  // 104 KB
    cudaFuncSetAttribute(knn_kernel, cudaFuncAttributeMaxDynamicSharedMemorySize,
                         KNN_SMEM);
    dim3 gknn(GG / QW, BB);
    knn_kernel<<<gknn, 256, KNN_SMEM>>>(xyz);

    cudaFuncSetAttribute(mlp_kernel, cudaFuncAttributeMaxDynamicSharedMemorySize,
                         MLP_SMEM);
    mlp_kernel<<<(BB * GG) / TM, 256, MLP_SMEM>>>(feat, W1, b1, W2, b2, out);
}

// round 3
// speedup vs baseline: 1.3438x; 1.0515x over previous
#include <cuda_runtime.h>
#include <math.h>

#define BB 16
#define GG 2048
#define CC 128
#define KK 16
#define TM 64          // rows per mlp block
#define QW 8           // queries (warps) per knn block
#define SCAP 1024      // survivor capacity per warp
#define MLP_T 128

__device__ int g_knn[BB * GG * KK];

// ---------------------------------------------------------------------------
// helpers
// ---------------------------------------------------------------------------
__device__ __forceinline__ unsigned okey(float d) {
    unsigned u = __float_as_uint(d);
    unsigned m = ((unsigned)(((int)u) >> 31)) | 0x80000000u;
    return u ^ m;
}
__device__ __forceinline__ unsigned long long dup2(float x) {
    unsigned long long r; unsigned a = __float_as_uint(x);
    asm("mov.b64 %0, {%1, %1};" : "=l"(r) : "r"(a));
    return r;
}
__device__ __forceinline__ float2 unpack2(unsigned long long v) {
    unsigned lo, hi;
    asm("mov.b64 {%0, %1}, %2;" : "=r"(lo), "=r"(hi) : "l"(v));
    return make_float2(__uint_as_float(lo), __uint_as_float(hi));
}
#define FMA2(acc, a, b) \
    asm("fma.rn.f32x2 %0, %1, %2, %0;" : "+l"(acc) : "l"(a), "l"(b))

// ---------------------------------------------------------------------------
// KNN: warp/query. Sample-threshold -> compact survivors -> ballot radix-select.
// Packed (key<<32)|idx gives exact lexicographic (dist, idx) order = top_k ties.
// ---------------------------------------------------------------------------
__global__ __launch_bounds__(256) void knn_kernel(const float* __restrict__ xyz) {
    extern __shared__ unsigned char ksm[];
    float4* pts = (float4*)ksm;                                  // 32KB
    unsigned long long* survAll = (unsigned long long*)(ksm + GG * 16);  // 64KB

    const int tid = threadIdx.x;
    const int b = blockIdx.y;
    const float* p = xyz + (size_t)b * GG * 3;
    for (int i = tid; i < GG; i += 256) {
        float x = p[i * 3 + 0], y = p[i * 3 + 1], z = p[i * 3 + 2];
        pts[i] = make_float4(x, y, z, x * x + y * y + z * z);
    }
    __syncthreads();

    const int w = tid >> 5, lane = tid & 31;
    const unsigned FULL = 0xffffffffu;
    const unsigned lmask = (1u << lane) - 1u;
    unsigned long long* sv = survAll + w * SCAP;

    const int q = blockIdx.x * QW + w;
    const float4 qp = pts[q];

    // ---- phase A: 256-point subsample, binary-search 16th key -> tau ----
    unsigned skey[8];
#pragma unroll
    for (int j = 0; j < 8; ++j) {
        int c = (j * 32 + lane) * 8;
        float4 pc = pts[c];
        float t = fmaf(qp.x, pc.x, fmaf(qp.y, pc.y, qp.z * pc.z));
        float d = fmaf(-2.f, t, qp.w + pc.w);
        skey[j] = okey(d);
    }
    unsigned lo = 0, hi = 0xffffffffu;
#pragma unroll
    for (int step = 0; step < 16; ++step) {
        unsigned mid = lo + ((hi - lo) >> 1);
        unsigned c = 0;
#pragma unroll
        for (int j = 0; j < 8; ++j) c += (skey[j] <= mid) ? 1u : 0u;
        c = __reduce_add_sync(FULL, c);
        if (c >= KK) hi = mid; else lo = mid + 1;
    }
    const unsigned tau = hi;   // >= sample 16th >= true 16th

    // ---- phase B: distance pass + compact survivors (key <= tau) ----
    unsigned scnt = 0;
    for (int j = 0; j < GG / 32; ++j) {
        int c = j * 32 + lane;
        float4 pc = pts[c];
        float t = fmaf(qp.x, pc.x, fmaf(qp.y, pc.y, qp.z * pc.z));
        float d = fmaf(-2.f, t, qp.w + pc.w);
        unsigned u = okey(d);
        bool sel = (u <= tau);
        unsigned m = __ballot_sync(FULL, sel);
        unsigned pos = scnt + __popc(m & lmask);
        if (sel && pos < SCAP)
            sv[pos] = ((unsigned long long)u << 32) | (unsigned)c;
        scnt += __popc(m);
    }
    if (scnt > SCAP) scnt = SCAP;
    unsigned padded = (scnt + 31u) & ~31u;
    for (unsigned i = scnt + lane; i < padded; i += 32) sv[i] = ~0ULL;
    __syncwarp();

    // ---- phase C: exact 16-smallest via 5-bit ballot radix on packed keys ----
    const int niter = padded >> 5;
    unsigned need = KK;
    unsigned long long prefix = 0;
    int s = 60;
    bool first = true;
    for (;;) {
        unsigned cntl = 0;
        for (int i = 0; i < niter; ++i) {
            unsigned long long pk = sv[i * 32 + lane];
            bool ok = first || ((pk >> (s + 5)) == prefix);
            unsigned d = (unsigned)(pk >> s) & 31u;
            unsigned mok = __ballot_sync(FULL, ok);
            unsigned m0 = __ballot_sync(FULL, ok && (d & 1u));
            unsigned m1 = __ballot_sync(FULL, ok && (d & 2u));
            unsigned m2 = __ballot_sync(FULL, ok && (d & 4u));
            unsigned m3 = __ballot_sync(FULL, ok && (d & 8u));
            unsigned m4 = __ballot_sync(FULL, ok && (d & 16u));
            unsigned sel = mok;
            sel &= (lane & 1)  ? m0 : ~m0;
            sel &= (lane & 2)  ? m1 : ~m1;
            sel &= (lane & 4)  ? m2 : ~m2;
            sel &= (lane & 8)  ? m3 : ~m3;
            sel &= (lane & 16) ? m4 : ~m4;
            cntl += __popc(sel);
        }
        unsigned run = cntl;
#pragma unroll
        for (int off = 1; off < 32; off <<= 1) {
            unsigned n = __shfl_up_sync(FULL, run, off);
            if (lane >= off) run += n;
        }
        unsigned excl = run - cntl;
        bool has = (excl < need) && (run >= need);
        unsigned hm = __ballot_sync(FULL, has);
        int src = __ffs(hm) - 1;
        unsigned base = __shfl_sync(FULL, excl, src);
        unsigned cnt  = __shfl_sync(FULL, cntl, src);
        prefix = (prefix << 5) | (unsigned)src;
        need -= base;
        first = false;
        if (need == cnt || s == 0) break;
        s -= 5;
    }

    // ---- emit: all packed with (pk >> s) <= prefix (exactly 16) ----
    unsigned outc = 0;
    int* outp = g_knn + ((size_t)b * GG + q) * KK;
    for (int i = 0; i < niter && outc < KK; ++i) {
        unsigned long long pk = sv[i * 32 + lane];
        bool sel = (pk >> s) <= prefix;
        unsigned m = __ballot_sync(FULL, sel);
        unsigned pos = outc + __popc(m & lmask);
        if (sel && pos < KK) outp[pos] = (int)(unsigned)pk;
        outc += __popc(m);
    }
}

// ---------------------------------------------------------------------------
// MLP: 128 threads, 64-row tile, 8x8 micro-tile, f32x2 FMAs (col pairs).
// ---------------------------------------------------------------------------
#define MLP_SMEM (TM * CC * 4 + CC * CC * 4 + 2 * CC * 4 + TM * KK * 4)

__device__ __forceinline__ void gemm_f32x2(const float* __restrict__ As,
                                           const float* __restrict__ Ws,
                                           int r0, int j0,
                                           unsigned long long (&acc)[8][4]) {
#pragma unroll
    for (int i = 0; i < 8; ++i)
#pragma unroll
        for (int pp = 0; pp < 4; ++pp) acc[i][pp] = 0ULL;

#pragma unroll 2
    for (int c = 0; c < CC; ++c) {
        const ulonglong2* wp = reinterpret_cast<const ulonglong2*>(Ws + c * CC + j0);
        ulonglong2 wA = wp[0], wB = wp[1];
        unsigned long long wv[4] = {wA.x, wA.y, wB.x, wB.y};
        unsigned long long av[8];
#pragma unroll
        for (int i = 0; i < 8; ++i) av[i] = dup2(As[(r0 + i) * CC + c]);
#pragma unroll
        for (int i = 0; i < 8; ++i)
#pragma unroll
            for (int pp = 0; pp < 4; ++pp)
                FMA2(acc[i][pp], av[i], wv[pp]);
    }
}

__global__ __launch_bounds__(MLP_T) void mlp_kernel(const float* __restrict__ feat,
                                                    const float* __restrict__ W1,
                                                    const float* __restrict__ b1,
                                                    const float* __restrict__ W2,
                                                    const float* __restrict__ b2,
                                                    float* __restrict__ out) {
    extern __shared__ __align__(16) float sm[];
    float* As   = sm;                  // TM * CC (row-major)
    float* Ws   = As + TM * CC;        // CC * CC
    float* bs   = Ws + CC * CC;        // 2 * CC
    int*   sidx = (int*)(bs + 2 * CC); // TM * KK

    const int tid = threadIdx.x;
    const int rowBase = blockIdx.x * TM;
    const int b = rowBase >> 11;
    const float* fb = feat + (size_t)b * GG * CC;

    for (int i = tid; i < TM * KK; i += MLP_T) sidx[i] = g_knn[(size_t)rowBase * KK + i];
    for (int i = tid; i < CC * CC / 4; i += MLP_T)
        ((float4*)Ws)[i] = ((const float4*)W1)[i];
    if (tid < CC) { bs[tid] = b1[tid]; bs[CC + tid] = b2[tid]; }
    __syncthreads();

    // gather + L2 pool -> As row-major (conflict-free float4 STS)
    {
        const int lane = tid & 31, warp = tid >> 5;
        for (int pass = 0; pass < TM / 4; ++pass) {
            const int r = pass * 4 + warp;
            const int* ip = sidx + r * KK;
            float4 acc = make_float4(0.f, 0.f, 0.f, 0.f);
#pragma unroll
            for (int k = 0; k < KK; ++k) {
                const float4 f = *reinterpret_cast<const float4*>(
                    fb + (size_t)ip[k] * CC + lane * 4);
                acc.x = fmaf(f.x, f.x, acc.x);
                acc.y = fmaf(f.y, f.y, acc.y);
                acc.z = fmaf(f.z, f.z, acc.z);
                acc.w = fmaf(f.w, f.w, acc.w);
            }
            acc.x = sqrtf(acc.x); acc.y = sqrtf(acc.y);
            acc.z = sqrtf(acc.z); acc.w = sqrtf(acc.w);
            *reinterpret_cast<float4*>(As + r * CC + lane * 4) = acc;
        }
    }
    __syncthreads();

    const int ty = tid >> 4, tx = tid & 15;
    const int r0 = ty * 8, j0 = tx * 8;

    unsigned long long acc[8][4];
    gemm_f32x2(As, Ws, r0, j0, acc);

    // GELU epilogue
    float g[8][8];
#pragma unroll
    for (int i = 0; i < 8; ++i)
#pragma unroll
        for (int pp = 0; pp < 4; ++pp) {
            float2 v = unpack2(acc[i][pp]);
            float vx = v.x + bs[j0 + pp * 2 + 0];
            float vy = v.y + bs[j0 + pp * 2 + 1];
            g[i][pp * 2 + 0] = 0.5f * vx * (1.f + erff(vx * 0.70710678118654752f));
            g[i][pp * 2 + 1] = 0.5f * vy * (1.f + erff(vy * 0.70710678118654752f));
        }
    __syncthreads();

    // H -> As, W2 -> Ws
#pragma unroll
    for (int i = 0; i < 8; ++i) {
        float* hp = As + (r0 + i) * CC + j0;
        *reinterpret_cast<float4*>(hp)     = make_float4(g[i][0], g[i][1], g[i][2], g[i][3]);
        *reinterpret_cast<float4*>(hp + 4) = make_float4(g[i][4], g[i][5], g[i][6], g[i][7]);
    }
    for (int i = tid; i < CC * CC / 4; i += MLP_T)
        ((float4*)Ws)[i] = ((const float4*)W2)[i];
    __syncthreads();

    unsigned long long acc2[8][4];
    gemm_f32x2(As, Ws, r0, j0, acc2);

#pragma unroll
    for (int i = 0; i < 8; ++i) {
        float o[8];
#pragma unroll
        for (int pp = 0; pp < 4; ++pp) {
            float2 v = unpack2(acc2[i][pp]);
            o[pp * 2 + 0] = v.x + bs[CC + j0 + pp * 2 + 0];
            o[pp * 2 + 1] = v.y + bs[CC + j0 + pp * 2 + 1];
        }
        float* op = out + (size_t)(rowBase + r0 + i) * CC + j0;
        *reinterpret_cast<float4*>(op)     = make_float4(o[0], o[1], o[2], o[3]);
        *reinterpret_cast<float4*>(op + 4) = make_float4(o[4], o[5], o[6], o[7]);
    }
}

// ---------------------------------------------------------------------------
extern "C" void kernel_launch(void* const* d_in, const int* in_sizes, int n_in,
                              void* d_out, int out_size) {
    const float* xyz  = (const float*)d_in[0];
    const float* feat = (const float*)d_in[1];
    const float* W1   = (const float*)d_in[2];
    const float* b1   = (const float*)d_in[3];
    const float* W2   = (const float*)d_in[4];
    const float* b2   = (const float*)d_in[5];
    float* out = (float*)d_out;

    const int KNN_SMEM = GG * 16 + QW * SCAP * 8;   // 96 KB
    cudaFuncSetAttribute(knn_kernel, cudaFuncAttributeMaxDynamicSharedMemorySize,
                         KNN_SMEM);
    dim3 gknn(GG / QW, BB);
    knn_kernel<<<gknn, 256, KNN_SMEM>>>(xyz);

    cudaFuncSetAttribute(mlp_kernel, cudaFuncAttributeMaxDynamicSharedMemorySize,
                         MLP_SMEM);
    mlp_kernel<<<(BB * GG) / TM, MLP_T, MLP_SMEM>>>(feat, W1, b1, W2, b2, out);
}